// round 2
// baseline (speedup 1.0000x reference)
#include <cuda_runtime.h>

// LocalAggregation: out[i,c] = max_k relu(bn2(relu(bn1(feat[idx[i,k]] @ W1 + b1)) @ W2 + b2))[c]
// Training-mode BN over the gathered 1.6M-row batch == count-weighted stats over 100k unique rows.
// MLP is row-wise -> compute once per unique feat row, then gather-max.

#define C_IN  64
#define C_MID 64
#define C_OUT 128
#define N_MAX 100000
#define EPS_BN 1e-5f

// ---- scratch (device globals; no allocations allowed) ----
__device__ int   g_cnt[N_MAX];
__device__ float g_Y[N_MAX * C_MID];       // pre-BN layer-1 activations per unique row
__device__ float g_Z[N_MAX * C_OUT];       // pre-BN layer-2 activations per unique row
__device__ float g_sum1[C_MID], g_sq1[C_MID];
__device__ float g_sum2[C_OUT], g_sq2[C_OUT];
__device__ float g_s1[C_MID],  g_t1[C_MID];
__device__ float g_s2[C_OUT],  g_t2[C_OUT];
__device__ int   g_is64;                   // 1 if idx buffer is int64, 0 if int32

// ---------------------------------------------------------------------------
__global__ void zero_kernel(int n) {
    int i = blockIdx.x * blockDim.x + threadIdx.x;
    if (i < n) g_cnt[i] = 0;
    if (i < C_MID) { g_sum1[i] = 0.f; g_sq1[i] = 0.f; }
    if (i < C_OUT) { g_sum2[i] = 0.f; g_sq2[i] = 0.f; }
}

// Detect idx dtype: int64 little-endian => odd int32 words (high halves) are all 0
// (values are nonneg < n). int32 data has random values there.
__global__ void detect_kernel(const void* idxp) {
    const int* w = (const int*)idxp;
    int t = threadIdx.x;                 // 1024 threads -> words 1,3,...,2047
    int any = (w[2 * t + 1] != 0) ? 1 : 0;
    int r = __syncthreads_or(any);
    if (t == 0) g_is64 = (r == 0) ? 1 : 0;
}

__global__ void hist_kernel(const void* idxp, int total) {
    int i = blockIdx.x * blockDim.x + threadIdx.x;
    if (i >= total) return;
    int v;
    if (g_is64) v = (int)((const long long*)idxp)[i];
    else        v = ((const int*)idxp)[i];
    atomicAdd(&g_cnt[v], 1);
}

// ---------------------------------------------------------------------------
// Y = feat @ W1 + b1   (per unique row), plus count-weighted sum / sumsq.
// blockDim = 256 = 4 row-lanes x 64 channels.
__global__ void gemm1_kernel(const float* __restrict__ feat,
                             const float* __restrict__ W1,
                             const float* __restrict__ b1, int n) {
    __shared__ float W1s[C_IN * C_MID];
    __shared__ float xs[4][C_IN];
    int tid = threadIdx.x;
    int rl = tid >> 6;        // 0..3
    int c  = tid & 63;        // channel
    for (int i = tid; i < C_IN * C_MID; i += 256) W1s[i] = W1[i];
    float bc = b1[c];
    float ws = 0.f, wq = 0.f;
    __syncthreads();
    for (int r0 = blockIdx.x * 4; r0 < n; r0 += gridDim.x * 4) {
        int r = r0 + rl;
        if (r < n) xs[rl][c] = feat[r * C_IN + c];
        __syncthreads();
        if (r < n) {
            float y = bc;
            #pragma unroll
            for (int d = 0; d < C_IN; d++)
                y = fmaf(xs[rl][d], W1s[d * C_MID + c], y);
            g_Y[r * C_MID + c] = y;
            float w = (float)g_cnt[r];
            ws = fmaf(w, y, ws);
            wq = fmaf(w, y * y, wq);
        }
        __syncthreads();
    }
    atomicAdd(&g_sum1[c], ws);
    atomicAdd(&g_sq1[c],  wq);
}

__global__ void finalize1_kernel(const float* __restrict__ g1,
                                 const float* __restrict__ be1, float invN) {
    int c = threadIdx.x;  // 64
    float mu  = g_sum1[c] * invN;
    float var = g_sq1[c] * invN - mu * mu;
    float s = g1[c] * rsqrtf(var + EPS_BN);
    g_s1[c] = s;
    g_t1[c] = be1[c] - mu * s;
}

// ---------------------------------------------------------------------------
// H = relu(Y*s1 + t1); Z = H @ W2 + b2; weighted stats of Z.
// blockDim = 256 = 2 row-lanes x 128 channels.
__global__ void gemm2_kernel(const float* __restrict__ W2,
                             const float* __restrict__ b2, int n) {
    __shared__ float W2s[C_MID * C_OUT];   // 32 KB
    __shared__ float hs[2][C_MID];
    int tid = threadIdx.x;
    int rl = tid >> 7;        // 0..1
    int c  = tid & 127;       // out channel
    for (int i = tid; i < C_MID * C_OUT; i += 256) W2s[i] = W2[i];
    float bc = b2[c];
    float s1c = 0.f, t1c = 0.f;
    if (c < C_MID) { s1c = g_s1[c]; t1c = g_t1[c]; }
    float ws = 0.f, wq = 0.f;
    __syncthreads();
    for (int r0 = blockIdx.x * 2; r0 < n; r0 += gridDim.x * 2) {
        int r = r0 + rl;
        if (r < n && c < C_MID) {
            float y = g_Y[r * C_MID + c];
            hs[rl][c] = fmaxf(fmaf(y, s1c, t1c), 0.f);
        }
        __syncthreads();
        if (r < n) {
            float z = bc;
            #pragma unroll
            for (int d = 0; d < C_MID; d++)
                z = fmaf(hs[rl][d], W2s[d * C_OUT + c], z);
            g_Z[r * C_OUT + c] = z;
            float w = (float)g_cnt[r];
            ws = fmaf(w, z, ws);
            wq = fmaf(w, z * z, wq);
        }
        __syncthreads();
    }
    atomicAdd(&g_sum2[c], ws);
    atomicAdd(&g_sq2[c],  wq);
}

__global__ void finalize2_kernel(const float* __restrict__ g2,
                                 const float* __restrict__ be2, float invN) {
    int c = threadIdx.x;  // 128
    float mu  = g_sum2[c] * invN;
    float var = g_sq2[c] * invN - mu * mu;
    float s = g2[c] * rsqrtf(var + EPS_BN);
    g_s2[c] = s;
    g_t2[c] = be2[c] - mu * s;
}

// ---------------------------------------------------------------------------
// out[i,c] = max_k relu(Z[idx[i,k],c]*s2[c] + t2[c]); relu folds into max(0, .).
__global__ void gather_max_kernel(const void* __restrict__ idxp,
                                  float* __restrict__ out, int n, int k) {
    __shared__ int ridx[32];
    int i = blockIdx.x;
    int c = threadIdx.x;  // 128
    if (c < k) {
        if (g_is64) ridx[c] = (int)((const long long*)idxp)[(size_t)i * k + c];
        else        ridx[c] = ((const int*)idxp)[(size_t)i * k + c];
    }
    float s = g_s2[c], t = g_t2[c];
    __syncthreads();
    float m = 0.f;   // relu lower bound
    #pragma unroll 4
    for (int j = 0; j < k; j++) {
        float z = g_Z[ridx[j] * C_OUT + c];
        m = fmaxf(m, fmaf(z, s, t));
    }
    out[(size_t)i * C_OUT + c] = m;
}

// ---------------------------------------------------------------------------
extern "C" void kernel_launch(void* const* d_in, const int* in_sizes, int n_in,
                              void* d_out, int out_size) {
    const float* feat = (const float*)d_in[0];
    const void*  idx  = d_in[1];
    const float* W1   = (const float*)d_in[2];
    const float* b1   = (const float*)d_in[3];
    const float* g1   = (const float*)d_in[4];
    const float* be1  = (const float*)d_in[5];
    const float* W2   = (const float*)d_in[6];
    const float* b2   = (const float*)d_in[7];
    const float* g2   = (const float*)d_in[8];
    const float* be2  = (const float*)d_in[9];
    float* out = (float*)d_out;

    int n = in_sizes[0] / C_IN;       // 100000
    int k = in_sizes[1] / n;          // 16
    int total = n * k;                // 1.6M
    float invN = 1.0f / (float)total;

    zero_kernel<<<(n + 255) / 256, 256>>>(n);
    detect_kernel<<<1, 1024>>>(idx);
    hist_kernel<<<(total + 255) / 256, 256>>>(idx, total);
    gemm1_kernel<<<2048, 256>>>(feat, W1, b1, n);
    finalize1_kernel<<<1, C_MID>>>(g1, be1, invN);
    gemm2_kernel<<<2048, 256>>>(W2, b2, n);
    finalize2_kernel<<<1, C_OUT>>>(g2, be2, invN);
    gather_max_kernel<<<n, C_OUT>>>(idx, out, n, k);
}

// round 7
// speedup vs baseline: 1.7372x; 1.7372x over previous
#include <cuda_runtime.h>
#include <cuda_fp16.h>

#define C_IN  64
#define C_MID 64
#define C_OUT 128
#define N_MAX 100000
#define EPS_BN 1e-5f

typedef unsigned long long ull;

// ---- scratch (device globals; no allocations allowed) ----
__device__ int    g_cnt[N_MAX];
__device__ __align__(16) float  g_Y[N_MAX * C_MID];     // pre-BN layer-1 activations
__device__ __align__(16) __half g_Zh[N_MAX * C_OUT];    // pre-BN layer-2 activations (fp16)
__device__ __align__(16) float g_sum1[C_MID], g_sq1[C_MID];
__device__ __align__(16) float g_sum2[C_OUT], g_sq2[C_OUT];
__device__ __align__(16) float g_s1[C_MID],  g_t1[C_MID];
__device__ __align__(16) float g_s2[C_OUT],  g_t2[C_OUT];
__device__ int   g_is64;

// ---- packed fp32x2 helpers (Blackwell FFMA2; ptxas won't auto-fuse) ----
__device__ __forceinline__ ull pack2(float lo, float hi) {
    ull r; asm("mov.b64 %0, {%1, %2};" : "=l"(r) : "f"(lo), "f"(hi)); return r;
}
__device__ __forceinline__ void unpack2(ull v, float& lo, float& hi) {
    asm("mov.b64 {%0, %1}, %2;" : "=f"(lo), "=f"(hi) : "l"(v));
}
__device__ __forceinline__ ull fma2(ull a, ull b, ull c) {
    ull d; asm("fma.rn.f32x2 %0, %1, %2, %3;" : "=l"(d) : "l"(a), "l"(b), "l"(c)); return d;
}

// ---------------------------------------------------------------------------
__global__ void zero_kernel(int n) {
    int i = blockIdx.x * blockDim.x + threadIdx.x;
    if (i < n) g_cnt[i] = 0;
    if (i < C_MID) { g_sum1[i] = 0.f; g_sq1[i] = 0.f; }
    if (i < C_OUT) { g_sum2[i] = 0.f; g_sq2[i] = 0.f; }
}

// int64 little-endian => odd int32 words (high halves) all zero (values < n).
__global__ void detect_kernel(const void* idxp) {
    const int* w = (const int*)idxp;
    int t = threadIdx.x;
    int any = (w[2 * t + 1] != 0) ? 1 : 0;
    int r = __syncthreads_or(any);
    if (t == 0) g_is64 = (r == 0) ? 1 : 0;
}

__global__ void hist_kernel(const void* idxp, int total) {
    int i = blockIdx.x * blockDim.x + threadIdx.x;
    if (i >= total) return;
    int v;
    if (g_is64) v = (int)((const long long*)idxp)[i];
    else        v = ((const int*)idxp)[i];
    atomicAdd(&g_cnt[v], 1);
}

// ---------------------------------------------------------------------------
// GEMM1: Y = feat @ W1 + b1, plus count-weighted sum/sumsq per output channel.
// Block: 256 threads = 16 ty (rows) x 16 tx (cols). Tile 64 rows x 64 cols.
// Thread tile: 4 rows x 4 cols, cols packed in fp32x2 pairs.
__global__ void __launch_bounds__(256) gemm1_kernel(const float* __restrict__ feat,
        const float* __restrict__ W1, const float* __restrict__ b1, int n) {
    __shared__ float Ws[C_IN * C_MID];      // [d][c] 16KB
    __shared__ float xs[C_IN * 68];         // [d][row], pad 68
    __shared__ float sW[C_MID], sQ[C_MID];
    int tid = threadIdx.x;
    int ty = tid >> 4, tx = tid & 15;
    int c0 = tx << 2;
    int rl = ty << 2;
    for (int i = tid; i < C_IN * C_MID; i += 256) Ws[i] = W1[i];
    if (tid < C_MID) { sW[tid] = 0.f; sQ[tid] = 0.f; }
    float4 bv = *(const float4*)(b1 + c0);
    ull binit0 = pack2(bv.x, bv.y), binit1 = pack2(bv.z, bv.w);
    float wsum[4] = {0,0,0,0}, wsq[4] = {0,0,0,0};
    __syncthreads();
    int ntiles = (n + 63) >> 6;
    for (int tile = blockIdx.x; tile < ntiles; tile += gridDim.x) {
        int rbase = tile << 6;
        // transpose-load feat tile
        #pragma unroll
        for (int p = 0; p < 4; p++) {
            int r = (p << 4) + ty;
            int gr = rbase + r; if (gr >= n) gr = n - 1;
            float4 v = *(const float4*)(feat + (size_t)gr * C_IN + c0);
            xs[(c0 + 0) * 68 + r] = v.x;
            xs[(c0 + 1) * 68 + r] = v.y;
            xs[(c0 + 2) * 68 + r] = v.z;
            xs[(c0 + 3) * 68 + r] = v.w;
        }
        __syncthreads();
        ull acc[4][2];
        #pragma unroll
        for (int i = 0; i < 4; i++) { acc[i][0] = binit0; acc[i][1] = binit1; }
        #pragma unroll
        for (int d = 0; d < C_IN; d++) {
            float4 xv = *(const float4*)&xs[d * 68 + rl];
            ulonglong2 wv = *(const ulonglong2*)&Ws[d * C_MID + c0];
            ull x0 = pack2(xv.x, xv.x), x1 = pack2(xv.y, xv.y);
            ull x2 = pack2(xv.z, xv.z), x3 = pack2(xv.w, xv.w);
            acc[0][0] = fma2(x0, wv.x, acc[0][0]); acc[0][1] = fma2(x0, wv.y, acc[0][1]);
            acc[1][0] = fma2(x1, wv.x, acc[1][0]); acc[1][1] = fma2(x1, wv.y, acc[1][1]);
            acc[2][0] = fma2(x2, wv.x, acc[2][0]); acc[2][1] = fma2(x2, wv.y, acc[2][1]);
            acc[3][0] = fma2(x3, wv.x, acc[3][0]); acc[3][1] = fma2(x3, wv.y, acc[3][1]);
        }
        #pragma unroll
        for (int i = 0; i < 4; i++) {
            int gr = rbase + rl + i;
            if (gr < n) {
                float y[4];
                unpack2(acc[i][0], y[0], y[1]);
                unpack2(acc[i][1], y[2], y[3]);
                *(float4*)(g_Y + (size_t)gr * C_MID + c0) = make_float4(y[0], y[1], y[2], y[3]);
                float w = (float)g_cnt[gr];
                #pragma unroll
                for (int j = 0; j < 4; j++) {
                    wsum[j] = fmaf(w, y[j], wsum[j]);
                    wsq[j]  = fmaf(w, y[j] * y[j], wsq[j]);
                }
            }
        }
        __syncthreads();
    }
    #pragma unroll
    for (int j = 0; j < 4; j++) {
        atomicAdd(&sW[c0 + j], wsum[j]);
        atomicAdd(&sQ[c0 + j], wsq[j]);
    }
    __syncthreads();
    if (tid < C_MID) {
        atomicAdd(&g_sum1[tid], sW[tid]);
        atomicAdd(&g_sq1[tid],  sQ[tid]);
    }
}

__global__ void finalize1_kernel(const float* __restrict__ g1,
                                 const float* __restrict__ be1, float invN) {
    int c = threadIdx.x;  // 64
    float mu  = g_sum1[c] * invN;
    float var = g_sq1[c] * invN - mu * mu;
    float s = g1[c] * rsqrtf(var + EPS_BN);
    g_s1[c] = s;
    g_t1[c] = be1[c] - mu * s;
}

// ---------------------------------------------------------------------------
// GEMM2: H = relu(Y*s1+t1) (fused into transpose-load); Z = H @ W2 + b2.
// Tile 64 rows x 128 cols; thread tile 4 rows x 8 cols (4 fp32x2 col-pairs).
// Z stored as fp16; stats accumulated in fp32 pre-rounding.
__global__ void __launch_bounds__(256) gemm2_kernel(const float* __restrict__ W2,
        const float* __restrict__ b2, int n) {
    __shared__ float Ws[C_MID * C_OUT];     // [d][c] 32KB
    __shared__ float hs[C_MID * 68];        // [d][row]
    __shared__ float sW[C_OUT], sQ[C_OUT];
    int tid = threadIdx.x;
    int ty = tid >> 4, tx = tid & 15;
    int c0 = tx << 3;
    int rl = ty << 2;
    for (int i = tid; i < C_MID * C_OUT; i += 256) Ws[i] = W2[i];
    if (tid < C_OUT) { sW[tid] = 0.f; sQ[tid] = 0.f; }
    float4 s1v = *(const float4*)&g_s1[tx << 2];
    float4 t1v = *(const float4*)&g_t1[tx << 2];
    float4 ba = *(const float4*)(b2 + c0);
    float4 bb = *(const float4*)(b2 + c0 + 4);
    ull binit[4] = { pack2(ba.x, ba.y), pack2(ba.z, ba.w),
                     pack2(bb.x, bb.y), pack2(bb.z, bb.w) };
    float wsum[8] = {0,0,0,0,0,0,0,0}, wsq[8] = {0,0,0,0,0,0,0,0};
    __syncthreads();
    int ntiles = (n + 63) >> 6;
    for (int tile = blockIdx.x; tile < ntiles; tile += gridDim.x) {
        int rbase = tile << 6;
        #pragma unroll
        for (int p = 0; p < 4; p++) {
            int r = (p << 4) + ty;
            int gr = rbase + r; if (gr >= n) gr = n - 1;
            float4 v = *(const float4*)(g_Y + (size_t)gr * C_MID + (tx << 2));
            int db = tx << 2;
            hs[(db + 0) * 68 + r] = fmaxf(fmaf(v.x, s1v.x, t1v.x), 0.f);
            hs[(db + 1) * 68 + r] = fmaxf(fmaf(v.y, s1v.y, t1v.y), 0.f);
            hs[(db + 2) * 68 + r] = fmaxf(fmaf(v.z, s1v.z, t1v.z), 0.f);
            hs[(db + 3) * 68 + r] = fmaxf(fmaf(v.w, s1v.w, t1v.w), 0.f);
        }
        __syncthreads();
        ull acc[4][4];
        #pragma unroll
        for (int i = 0; i < 4; i++)
            #pragma unroll
            for (int jp = 0; jp < 4; jp++) acc[i][jp] = binit[jp];
        #pragma unroll
        for (int d = 0; d < C_MID; d++) {
            float4 xv = *(const float4*)&hs[d * 68 + rl];
            ulonglong2 wa = *(const ulonglong2*)&Ws[d * C_OUT + c0];
            ulonglong2 wb = *(const ulonglong2*)&Ws[d * C_OUT + c0 + 4];
            ull x0 = pack2(xv.x, xv.x), x1 = pack2(xv.y, xv.y);
            ull x2 = pack2(xv.z, xv.z), x3 = pack2(xv.w, xv.w);
            acc[0][0] = fma2(x0, wa.x, acc[0][0]); acc[0][1] = fma2(x0, wa.y, acc[0][1]);
            acc[0][2] = fma2(x0, wb.x, acc[0][2]); acc[0][3] = fma2(x0, wb.y, acc[0][3]);
            acc[1][0] = fma2(x1, wa.x, acc[1][0]); acc[1][1] = fma2(x1, wa.y, acc[1][1]);
            acc[1][2] = fma2(x1, wb.x, acc[1][2]); acc[1][3] = fma2(x1, wb.y, acc[1][3]);
            acc[2][0] = fma2(x2, wa.x, acc[2][0]); acc[2][1] = fma2(x2, wa.y, acc[2][1]);
            acc[2][2] = fma2(x2, wb.x, acc[2][2]); acc[2][3] = fma2(x2, wb.y, acc[2][3]);
            acc[3][0] = fma2(x3, wa.x, acc[3][0]); acc[3][1] = fma2(x3, wa.y, acc[3][1]);
            acc[3][2] = fma2(x3, wb.x, acc[3][2]); acc[3][3] = fma2(x3, wb.y, acc[3][3]);
        }
        #pragma unroll
        for (int i = 0; i < 4; i++) {
            int gr = rbase + rl + i;
            if (gr < n) {
                float z[8];
                unpack2(acc[i][0], z[0], z[1]);
                unpack2(acc[i][1], z[2], z[3]);
                unpack2(acc[i][2], z[4], z[5]);
                unpack2(acc[i][3], z[6], z[7]);
                __half2 h0 = __floats2half2_rn(z[0], z[1]);
                __half2 h1 = __floats2half2_rn(z[2], z[3]);
                __half2 h2 = __floats2half2_rn(z[4], z[5]);
                __half2 h3 = __floats2half2_rn(z[6], z[7]);
                uint4 u;
                u.x = *reinterpret_cast<unsigned*>(&h0);
                u.y = *reinterpret_cast<unsigned*>(&h1);
                u.z = *reinterpret_cast<unsigned*>(&h2);
                u.w = *reinterpret_cast<unsigned*>(&h3);
                *(uint4*)(g_Zh + (size_t)gr * C_OUT + c0) = u;
                float w = (float)g_cnt[gr];
                #pragma unroll
                for (int j = 0; j < 8; j++) {
                    wsum[j] = fmaf(w, z[j], wsum[j]);
                    wsq[j]  = fmaf(w, z[j] * z[j], wsq[j]);
                }
            }
        }
        __syncthreads();
    }
    #pragma unroll
    for (int j = 0; j < 8; j++) {
        atomicAdd(&sW[c0 + j], wsum[j]);
        atomicAdd(&sQ[c0 + j], wsq[j]);
    }
    __syncthreads();
    if (tid < C_OUT) {
        atomicAdd(&g_sum2[tid], sW[tid]);
        atomicAdd(&g_sq2[tid],  sQ[tid]);
    }
}

__global__ void finalize2_kernel(const float* __restrict__ g2,
                                 const float* __restrict__ be2, float invN) {
    int c = threadIdx.x;  // 128
    float mu  = g_sum2[c] * invN;
    float var = g_sq2[c] * invN - mu * mu;
    float s = g2[c] * rsqrtf(var + EPS_BN);
    g_s2[c] = s;
    g_t2[c] = be2[c] - mu * s;
}

// ---------------------------------------------------------------------------
// out[i,c] = max_k relu(Zh[idx[i,k],c]*s2[c] + t2[c]).
// 4 points/block, 64 threads per point, each thread owns a channel pair (half2).
__global__ void __launch_bounds__(256) gather_max_kernel(const void* __restrict__ idxp,
        float* __restrict__ out, int n, int k) {
    __shared__ int ridx[4][32];
    int tid = threadIdx.x;
    int g  = tid >> 6;      // point slot 0..3
    int c2 = tid & 63;      // half2 channel index (channels 2c2, 2c2+1)
    int i = blockIdx.x * 4 + g;
    bool valid = i < n;
    if (valid && c2 < k) {
        if (g_is64) ridx[g][c2] = (int)((const long long*)idxp)[(size_t)i * k + c2];
        else        ridx[g][c2] = ((const int*)idxp)[(size_t)i * k + c2];
    }
    float2 s = *(const float2*)&g_s2[c2 * 2];
    float2 t = *(const float2*)&g_t2[c2 * 2];
    __syncthreads();
    if (!valid) return;
    float m0 = 0.f, m1 = 0.f;   // relu lower bound
    #pragma unroll 8
    for (int j = 0; j < k; j++) {
        __half2 h = *(const __half2*)(g_Zh + (size_t)ridx[g][j] * C_OUT + c2 * 2);
        float2 z = __half22float2(h);
        m0 = fmaxf(m0, fmaf(z.x, s.x, t.x));
        m1 = fmaxf(m1, fmaf(z.y, s.y, t.y));
    }
    *(float2*)(out + (size_t)i * C_OUT + c2 * 2) = make_float2(m0, m1);
}

// ---------------------------------------------------------------------------
extern "C" void kernel_launch(void* const* d_in, const int* in_sizes, int n_in,
                              void* d_out, int out_size) {
    const float* feat = (const float*)d_in[0];
    const void*  idx  = d_in[1];
    const float* W1   = (const float*)d_in[2];
    const float* b1   = (const float*)d_in[3];
    const float* g1   = (const float*)d_in[4];
    const float* be1  = (const float*)d_in[5];
    const float* W2   = (const float*)d_in[6];
    const float* b2   = (const float*)d_in[7];
    const float* g2   = (const float*)d_in[8];
    const float* be2  = (const float*)d_in[9];
    float* out = (float*)d_out;

    int n = in_sizes[0] / C_IN;       // 100000
    int k = in_sizes[1] / n;          // 16
    int total = n * k;                // 1.6M
    float invN = 1.0f / (float)total;

    zero_kernel<<<(n + 255) / 256, 256>>>(n);
    detect_kernel<<<1, 1024>>>(idx);
    hist_kernel<<<(total + 255) / 256, 256>>>(idx, total);
    gemm1_kernel<<<782, 256>>>(feat, W1, b1, n);
    finalize1_kernel<<<1, C_MID>>>(g1, be1, invN);
    gemm2_kernel<<<444, 256>>>(W2, b2, n);
    finalize2_kernel<<<1, C_OUT>>>(g2, be2, invN);
    gather_max_kernel<<<(n + 3) / 4, 256>>>(idx, out, n, k);
}

// round 8
// speedup vs baseline: 2.1701x; 1.2492x over previous
#include <cuda_runtime.h>
#include <cuda_fp16.h>

#define C_IN  64
#define C_MID 64
#define C_OUT 128
#define N_MAX 100000
#define EPS_BN 1e-5f

typedef unsigned long long ull;

// ---- scratch (device globals; no allocations allowed) ----
__device__ int    g_cnt[N_MAX];
__device__ __align__(16) float  g_Y[N_MAX * C_MID];     // pre-BN layer-1 activations
__device__ __align__(16) __half g_Zh[N_MAX * C_OUT];    // pre-BN layer-2 activations (fp16)
__device__ __align__(16) float g_sum1[C_MID], g_sq1[C_MID];
__device__ __align__(16) float g_sum2[C_OUT], g_sq2[C_OUT];
__device__ __align__(16) float g_s1[C_MID],  g_t1[C_MID];
__device__ __align__(16) float g_s2[C_OUT],  g_t2[C_OUT];
__device__ int   g_is64;

// ---- packed fp32x2 helpers (Blackwell FFMA2; ptxas won't auto-fuse) ----
__device__ __forceinline__ ull pack2(float lo, float hi) {
    ull r; asm("mov.b64 %0, {%1, %2};" : "=l"(r) : "f"(lo), "f"(hi)); return r;
}
__device__ __forceinline__ void unpack2(ull v, float& lo, float& hi) {
    asm("mov.b64 {%0, %1}, %2;" : "=f"(lo), "=f"(hi) : "l"(v));
}
__device__ __forceinline__ ull fma2(ull a, ull b, ull c) {
    ull d; asm("fma.rn.f32x2 %0, %1, %2, %3;" : "=l"(d) : "l"(a), "l"(b), "l"(c)); return d;
}

// ---------------------------------------------------------------------------
__global__ void zero_kernel(int n) {
    int i = blockIdx.x * blockDim.x + threadIdx.x;
    if (i < n) g_cnt[i] = 0;
    if (i < C_MID) { g_sum1[i] = 0.f; g_sq1[i] = 0.f; }
    if (i < C_OUT) { g_sum2[i] = 0.f; g_sq2[i] = 0.f; }
}

// int64 little-endian => odd int32 words (high halves) all zero (values < n).
__global__ void detect_kernel(const void* idxp) {
    const int* w = (const int*)idxp;
    int t = threadIdx.x;
    int any = (w[2 * t + 1] != 0) ? 1 : 0;
    int r = __syncthreads_or(any);
    if (t == 0) g_is64 = (r == 0) ? 1 : 0;
}

__global__ void hist_kernel(const void* idxp, int total) {
    int i = blockIdx.x * blockDim.x + threadIdx.x;
    if (i >= total) return;
    int v;
    if (g_is64) v = (int)((const long long*)idxp)[i];
    else        v = ((const int*)idxp)[i];
    atomicAdd(&g_cnt[v], 1);
}

// ---------------------------------------------------------------------------
// GEMM1: Y = feat @ W1 + b1, plus count-weighted sum/sumsq per output channel.
// Block tile: 128 rows x 64 cols. Thread: 8 rows (4 f32x2 row-pairs) x 4 cols.
// xs transposed [d][r] with conflict-free loader (lane-consecutive r).
#define T1_PAD 132
__global__ void __launch_bounds__(256, 3) gemm1_kernel(const float* __restrict__ feat,
        const float* __restrict__ W1, const float* __restrict__ b1, int n) {
    __shared__ float Ws[C_IN * C_MID];      // [d][c] 16KB
    __shared__ float xs[C_IN * T1_PAD];     // [d][r] 33.8KB
    __shared__ float sW[C_MID], sQ[C_MID];
    int tid = threadIdx.x;
    int tx = tid & 15, ty = tid >> 4;
    int c0 = tx << 2;         // 4 cols
    int r0 = ty << 3;         // 8 rows
    int lr = tid & 127;       // loader: row within tile
    int dh = (tid >> 7) << 5; // loader: d base (0 or 32)
    for (int i = tid; i < C_IN * C_MID; i += 256) Ws[i] = W1[i];
    if (tid < C_MID) { sW[tid] = 0.f; sQ[tid] = 0.f; }
    float4 bv = *(const float4*)(b1 + c0);
    float wsum[4] = {0,0,0,0}, wsq[4] = {0,0,0,0};
    __syncthreads();
    int ntiles = (n + 127) >> 7;
    for (int tile = blockIdx.x; tile < ntiles; tile += gridDim.x) {
        int rbase = tile << 7;
        {   // transpose-load: thread owns one row-half; STS lanes consecutive in r
            int gr = rbase + lr; if (gr >= n) gr = n - 1;
            const float4* frow = (const float4*)(feat + (size_t)gr * C_IN + dh);
            #pragma unroll
            for (int u = 0; u < 8; u++) {
                float4 v = frow[u];
                int d = dh + (u << 2);
                xs[(d + 0) * T1_PAD + lr] = v.x;
                xs[(d + 1) * T1_PAD + lr] = v.y;
                xs[(d + 2) * T1_PAD + lr] = v.z;
                xs[(d + 3) * T1_PAD + lr] = v.w;
            }
        }
        __syncthreads();
        ull acc[4][4];
        #pragma unroll
        for (int rp = 0; rp < 4; rp++) {
            acc[rp][0] = pack2(bv.x, bv.x); acc[rp][1] = pack2(bv.y, bv.y);
            acc[rp][2] = pack2(bv.z, bv.z); acc[rp][3] = pack2(bv.w, bv.w);
        }
        #pragma unroll 16
        for (int d = 0; d < C_IN; d++) {
            ulonglong2 xA = *(const ulonglong2*)&xs[d * T1_PAD + r0];
            ulonglong2 xB = *(const ulonglong2*)&xs[d * T1_PAD + r0 + 4];
            float4 wv = *(const float4*)&Ws[d * C_MID + c0];
            ull w0 = pack2(wv.x, wv.x), w1 = pack2(wv.y, wv.y);
            ull w2 = pack2(wv.z, wv.z), w3 = pack2(wv.w, wv.w);
            acc[0][0] = fma2(xA.x, w0, acc[0][0]); acc[0][1] = fma2(xA.x, w1, acc[0][1]);
            acc[0][2] = fma2(xA.x, w2, acc[0][2]); acc[0][3] = fma2(xA.x, w3, acc[0][3]);
            acc[1][0] = fma2(xA.y, w0, acc[1][0]); acc[1][1] = fma2(xA.y, w1, acc[1][1]);
            acc[1][2] = fma2(xA.y, w2, acc[1][2]); acc[1][3] = fma2(xA.y, w3, acc[1][3]);
            acc[2][0] = fma2(xB.x, w0, acc[2][0]); acc[2][1] = fma2(xB.x, w1, acc[2][1]);
            acc[2][2] = fma2(xB.x, w2, acc[2][2]); acc[2][3] = fma2(xB.x, w3, acc[2][3]);
            acc[3][0] = fma2(xB.y, w0, acc[3][0]); acc[3][1] = fma2(xB.y, w1, acc[3][1]);
            acc[3][2] = fma2(xB.y, w2, acc[3][2]); acc[3][3] = fma2(xB.y, w3, acc[3][3]);
        }
        #pragma unroll
        for (int rp = 0; rp < 4; rp++) {
            int rA = rbase + r0 + (rp << 1);
            float ya[4], yb[4];
            #pragma unroll
            for (int j = 0; j < 4; j++) unpack2(acc[rp][j], ya[j], yb[j]);
            if (rA < n) {
                *(float4*)(g_Y + (size_t)rA * C_MID + c0) = make_float4(ya[0], ya[1], ya[2], ya[3]);
                float w = (float)g_cnt[rA];
                #pragma unroll
                for (int j = 0; j < 4; j++) {
                    wsum[j] = fmaf(w, ya[j], wsum[j]);
                    wsq[j]  = fmaf(w, ya[j] * ya[j], wsq[j]);
                }
            }
            if (rA + 1 < n) {
                *(float4*)(g_Y + (size_t)(rA + 1) * C_MID + c0) = make_float4(yb[0], yb[1], yb[2], yb[3]);
                float w = (float)g_cnt[rA + 1];
                #pragma unroll
                for (int j = 0; j < 4; j++) {
                    wsum[j] = fmaf(w, yb[j], wsum[j]);
                    wsq[j]  = fmaf(w, yb[j] * yb[j], wsq[j]);
                }
            }
        }
        __syncthreads();
    }
    #pragma unroll
    for (int j = 0; j < 4; j++) {
        atomicAdd(&sW[c0 + j], wsum[j]);
        atomicAdd(&sQ[c0 + j], wsq[j]);
    }
    __syncthreads();
    if (tid < C_MID) {
        atomicAdd(&g_sum1[tid], sW[tid]);
        atomicAdd(&g_sq1[tid],  sQ[tid]);
    }
}

__global__ void finalize1_kernel(const float* __restrict__ g1,
                                 const float* __restrict__ be1, float invN) {
    int c = threadIdx.x;  // 64
    float mu  = g_sum1[c] * invN;
    float var = g_sq1[c] * invN - mu * mu;
    float s = g1[c] * rsqrtf(var + EPS_BN);
    g_s1[c] = s;
    g_t1[c] = be1[c] - mu * s;
}

// ---------------------------------------------------------------------------
// GEMM2: H = relu(Y*s1+t1) fused into loader; Z = H @ W2 + b2; Z stored fp16.
// Block tile: 128 rows x 128 cols. Thread: 8 rows (4 pairs) x 8 cols.
// Dynamic shared: Wsh[64*128] | hs[64*132] | s1s[64] | t1s[64] | sW[128] | sQ[128]
#define T2_PAD 132
#define SMEM2_FLOATS (C_MID * C_OUT + C_MID * T2_PAD + C_MID + C_MID + C_OUT + C_OUT)
__global__ void __launch_bounds__(256, 2) gemm2_kernel(const float* __restrict__ W2,
        const float* __restrict__ b2, int n) {
    extern __shared__ float sm[];
    float* Wsh = sm;                              // 8192
    float* hs  = sm + C_MID * C_OUT;              // 8448
    float* s1s = hs + C_MID * T2_PAD;             // 64
    float* t1s = s1s + C_MID;                     // 64
    float* sW  = t1s + C_MID;                     // 128
    float* sQ  = sW + C_OUT;                      // 128
    int tid = threadIdx.x;
    int tx = tid & 15, ty = tid >> 4;
    int c0 = tx << 3;         // 8 cols
    int r0 = ty << 3;         // 8 rows
    int lr = tid & 127;
    int dh = (tid >> 7) << 5;
    for (int i = tid; i < C_MID * C_OUT; i += 256) Wsh[i] = W2[i];
    if (tid < C_MID) { s1s[tid] = g_s1[tid]; t1s[tid] = g_t1[tid]; }
    if (tid < C_OUT) { sW[tid] = 0.f; sQ[tid] = 0.f; }
    float bc[8];
    {
        float4 ba = *(const float4*)(b2 + c0);
        float4 bb = *(const float4*)(b2 + c0 + 4);
        bc[0]=ba.x; bc[1]=ba.y; bc[2]=ba.z; bc[3]=ba.w;
        bc[4]=bb.x; bc[5]=bb.y; bc[6]=bb.z; bc[7]=bb.w;
    }
    float wsum[8] = {0,0,0,0,0,0,0,0}, wsq[8] = {0,0,0,0,0,0,0,0};
    __syncthreads();
    int ntiles = (n + 127) >> 7;
    for (int tile = blockIdx.x; tile < ntiles; tile += gridDim.x) {
        int rbase = tile << 7;
        {   // loader: BN1 + relu fused, conflict-free transpose STS
            int gr = rbase + lr; if (gr >= n) gr = n - 1;
            const float4* yrow = (const float4*)(g_Y + (size_t)gr * C_MID + dh);
            #pragma unroll
            for (int u = 0; u < 8; u++) {
                float4 v = yrow[u];
                int d = dh + (u << 2);
                hs[(d + 0) * T2_PAD + lr] = fmaxf(fmaf(v.x, s1s[d + 0], t1s[d + 0]), 0.f);
                hs[(d + 1) * T2_PAD + lr] = fmaxf(fmaf(v.y, s1s[d + 1], t1s[d + 1]), 0.f);
                hs[(d + 2) * T2_PAD + lr] = fmaxf(fmaf(v.z, s1s[d + 2], t1s[d + 2]), 0.f);
                hs[(d + 3) * T2_PAD + lr] = fmaxf(fmaf(v.w, s1s[d + 3], t1s[d + 3]), 0.f);
            }
        }
        __syncthreads();
        ull acc[4][8];
        #pragma unroll
        for (int rp = 0; rp < 4; rp++)
            #pragma unroll
            for (int j = 0; j < 8; j++) acc[rp][j] = pack2(bc[j], bc[j]);
        #pragma unroll 16
        for (int d = 0; d < C_MID; d++) {
            ulonglong2 xA = *(const ulonglong2*)&hs[d * T2_PAD + r0];
            ulonglong2 xB = *(const ulonglong2*)&hs[d * T2_PAD + r0 + 4];
            ull xp[4] = { xA.x, xA.y, xB.x, xB.y };
            float4 wa = *(const float4*)&Wsh[d * C_OUT + c0];
            float4 wb = *(const float4*)&Wsh[d * C_OUT + c0 + 4];
            ull wd[8] = { pack2(wa.x,wa.x), pack2(wa.y,wa.y), pack2(wa.z,wa.z), pack2(wa.w,wa.w),
                          pack2(wb.x,wb.x), pack2(wb.y,wb.y), pack2(wb.z,wb.z), pack2(wb.w,wb.w) };
            #pragma unroll
            for (int rp = 0; rp < 4; rp++)
                #pragma unroll
                for (int j = 0; j < 8; j++)
                    acc[rp][j] = fma2(xp[rp], wd[j], acc[rp][j]);
        }
        #pragma unroll
        for (int rp = 0; rp < 4; rp++) {
            int rA = rbase + r0 + (rp << 1);
            float za[8], zb[8];
            #pragma unroll
            for (int j = 0; j < 8; j++) unpack2(acc[rp][j], za[j], zb[j]);
            if (rA < n) {
                __half2 h0 = __floats2half2_rn(za[0], za[1]);
                __half2 h1 = __floats2half2_rn(za[2], za[3]);
                __half2 h2 = __floats2half2_rn(za[4], za[5]);
                __half2 h3 = __floats2half2_rn(za[6], za[7]);
                uint4 u;
                u.x = *reinterpret_cast<unsigned*>(&h0); u.y = *reinterpret_cast<unsigned*>(&h1);
                u.z = *reinterpret_cast<unsigned*>(&h2); u.w = *reinterpret_cast<unsigned*>(&h3);
                *(uint4*)(g_Zh + (size_t)rA * C_OUT + c0) = u;
                float w = (float)g_cnt[rA];
                #pragma unroll
                for (int j = 0; j < 8; j++) {
                    wsum[j] = fmaf(w, za[j], wsum[j]);
                    wsq[j]  = fmaf(w, za[j] * za[j], wsq[j]);
                }
            }
            if (rA + 1 < n) {
                __half2 h0 = __floats2half2_rn(zb[0], zb[1]);
                __half2 h1 = __floats2half2_rn(zb[2], zb[3]);
                __half2 h2 = __floats2half2_rn(zb[4], zb[5]);
                __half2 h3 = __floats2half2_rn(zb[6], zb[7]);
                uint4 u;
                u.x = *reinterpret_cast<unsigned*>(&h0); u.y = *reinterpret_cast<unsigned*>(&h1);
                u.z = *reinterpret_cast<unsigned*>(&h2); u.w = *reinterpret_cast<unsigned*>(&h3);
                *(uint4*)(g_Zh + (size_t)(rA + 1) * C_OUT + c0) = u;
                float w = (float)g_cnt[rA + 1];
                #pragma unroll
                for (int j = 0; j < 8; j++) {
                    wsum[j] = fmaf(w, zb[j], wsum[j]);
                    wsq[j]  = fmaf(w, zb[j] * zb[j], wsq[j]);
                }
            }
        }
        __syncthreads();
    }
    #pragma unroll
    for (int j = 0; j < 8; j++) {
        atomicAdd(&sW[c0 + j], wsum[j]);
        atomicAdd(&sQ[c0 + j], wsq[j]);
    }
    __syncthreads();
    if (tid < C_OUT) {
        atomicAdd(&g_sum2[tid], sW[tid]);
        atomicAdd(&g_sq2[tid],  sQ[tid]);
    }
}

__global__ void finalize2_kernel(const float* __restrict__ g2,
                                 const float* __restrict__ be2, float invN) {
    int c = threadIdx.x;  // 128
    float mu  = g_sum2[c] * invN;
    float var = g_sq2[c] * invN - mu * mu;
    float s = g2[c] * rsqrtf(var + EPS_BN);
    g_s2[c] = s;
    g_t2[c] = be2[c] - mu * s;
}

// ---------------------------------------------------------------------------
// out[i,c] = max_k relu(Zh[idx[i,k],c]*s2[c] + t2[c]).
__global__ void __launch_bounds__(256) gather_max_kernel(const void* __restrict__ idxp,
        float* __restrict__ out, int n, int k) {
    __shared__ int ridx[4][32];
    int tid = threadIdx.x;
    int g  = tid >> 6;      // point slot 0..3
    int c2 = tid & 63;      // half2 channel index
    int i = blockIdx.x * 4 + g;
    bool valid = i < n;
    if (valid && c2 < k) {
        if (g_is64) ridx[g][c2] = (int)((const long long*)idxp)[(size_t)i * k + c2];
        else        ridx[g][c2] = ((const int*)idxp)[(size_t)i * k + c2];
    }
    float2 s = *(const float2*)&g_s2[c2 * 2];
    float2 t = *(const float2*)&g_t2[c2 * 2];
    __syncthreads();
    if (!valid) return;
    float m0 = 0.f, m1 = 0.f;   // relu lower bound
    #pragma unroll 8
    for (int j = 0; j < k; j++) {
        __half2 h = *(const __half2*)(g_Zh + (size_t)ridx[g][j] * C_OUT + c2 * 2);
        float2 z = __half22float2(h);
        m0 = fmaxf(m0, fmaf(z.x, s.x, t.x));
        m1 = fmaxf(m1, fmaf(z.y, s.y, t.y));
    }
    *(float2*)(out + (size_t)i * C_OUT + c2 * 2) = make_float2(m0, m1);
}

// ---------------------------------------------------------------------------
extern "C" void kernel_launch(void* const* d_in, const int* in_sizes, int n_in,
                              void* d_out, int out_size) {
    const float* feat = (const float*)d_in[0];
    const void*  idx  = d_in[1];
    const float* W1   = (const float*)d_in[2];
    const float* b1   = (const float*)d_in[3];
    const float* g1   = (const float*)d_in[4];
    const float* be1  = (const float*)d_in[5];
    const float* W2   = (const float*)d_in[6];
    const float* b2   = (const float*)d_in[7];
    const float* g2   = (const float*)d_in[8];
    const float* be2  = (const float*)d_in[9];
    float* out = (float*)d_out;

    int n = in_sizes[0] / C_IN;       // 100000
    int k = in_sizes[1] / n;          // 16
    int total = n * k;                // 1.6M
    float invN = 1.0f / (float)total;

    static bool attr_done = false;
    if (!attr_done) {
        cudaFuncSetAttribute(gemm2_kernel, cudaFuncAttributeMaxDynamicSharedMemorySize,
                             SMEM2_FLOATS * (int)sizeof(float));
        attr_done = true;
    }

    zero_kernel<<<(n + 255) / 256, 256>>>(n);
    detect_kernel<<<1, 1024>>>(idx);
    hist_kernel<<<(total + 255) / 256, 256>>>(idx, total);
    gemm1_kernel<<<444, 256>>>(feat, W1, b1, n);
    finalize1_kernel<<<1, C_MID>>>(g1, be1, invN);
    gemm2_kernel<<<296, 256, SMEM2_FLOATS * sizeof(float)>>>(W2, b2, n);
    finalize2_kernel<<<1, C_OUT>>>(g2, be2, invN);
    gather_max_kernel<<<(n + 3) / 4, 256>>>(idx, out, n, k);
}